// round 3
// baseline (speedup 1.0000x reference)
#include <cuda_runtime.h>
#include <math.h>

#define WPB 8           // warps per block
#define NC  1000        // classes
#define NK  10          // attack classes per row

__global__ __launch_bounds__(WPB * 32)
void boilerplate_loss_kernel(const float* __restrict__ y_pred,
                             const int*   __restrict__ y_attack,
                             float*       __restrict__ out,
                             int nrows)
{
    __shared__ unsigned int smask[WPB][32];   // 1000-bit attack mask per warp/row

    const int warp = threadIdx.x >> 5;
    const int lane = threadIdx.x & 31;
    const int row  = blockIdx.x * WPB + warp;
    if (row >= nrows) return;

    // --- build attack bitmask + gather attack logits (lanes 0..9) ---
    smask[warp][lane] = 0u;
    __syncwarp();

    float xa = 0.0f;
    if (lane < NK) {
        int idx = y_attack[row * NK + lane];
        xa = __ldg(&y_pred[(size_t)row * NC + idx]);
        atomicOr(&smask[warp][idx >> 5], 1u << (idx & 31));
    }
    __syncwarp();

    // --- single pass: sum(exp(x)) and max over non-attack logits ---
    const float4* rowp = reinterpret_cast<const float4*>(y_pred + (size_t)row * NC);
    float s  = 0.0f;
    float mx = -INFINITY;
    #pragma unroll 4
    for (int i = lane; i < NC / 4; i += 32) {
        float4 v = rowp[i];
        unsigned int bits = (smask[warp][i >> 3] >> ((i & 7) * 4)) & 0xFu;
        s += __expf(v.x); if (!(bits & 1u)) mx = fmaxf(mx, v.x);
        s += __expf(v.y); if (!(bits & 2u)) mx = fmaxf(mx, v.y);
        s += __expf(v.z); if (!(bits & 4u)) mx = fmaxf(mx, v.z);
        s += __expf(v.w); if (!(bits & 8u)) mx = fmaxf(mx, v.w);
    }
    #pragma unroll
    for (int o = 16; o > 0; o >>= 1) {
        s += __shfl_xor_sync(0xffffffffu, s, o);
        mx = fmaxf(mx, __shfl_xor_sync(0xffffffffu, mx, o));
    }

    // --- attack probs, min, macro loss ---
    float p = (lane < NK) ? (__expf(xa) / s) : INFINITY;
    float pmin = p;
    #pragma unroll
    for (int o = 16; o > 0; o >>= 1)
        pmin = fminf(pmin, __shfl_xor_sync(0xffffffffu, pmin, o));
    float pmax_non = __expf(mx) / s;
    float macro = pmax_non - pmin;                     // fp32, as reference

    // --- sorting term: diffs of consecutive attack probs, gen-mean p=9 (fp64 interior) ---
    float pnext = __shfl_down_sync(0xffffffffu, p, 1);
    double term = 0.0;
    if (lane < NK - 1) {
        float d  = pnext - p;                          // fp32 diff
        float sv = 5.0f + 5.0f * d;                    // fp32 surject
        term = pow((double)sv, 9.0);
    }
    #pragma unroll
    for (int o = 16; o > 0; o >>= 1)
        term += __shfl_xor_sync(0xffffffffu, term, o);

    if (lane == 0) {
        double gm9 = pow(term / 9.0, 1.0 / 9.0);
        float sorting = ((float)gm9 - 5.0f) / 5.0f;    // cast back to fp32, then surject
        float c0 = 5.0f + 5.0f * macro;
        float c1 = 5.0f + 5.0f * sorting;
        double m = (pow((double)c0, 10.0) + pow((double)c1, 10.0)) * 0.5;
        float fin = (float)pow(m, 1.0 / 10.0);
        out[row] = (fin - 5.0f) / 5.0f;
    }
}

extern "C" void kernel_launch(void* const* d_in, const int* in_sizes, int n_in,
                              void* d_out, int out_size)
{
    const float* y_pred   = (const float*)d_in[0];
    const int*   y_attack = (const int*)d_in[1];
    float*       out      = (float*)d_out;
    int nrows = in_sizes[1] / NK;   // 32768

    int blocks = (nrows + WPB - 1) / WPB;
    boilerplate_loss_kernel<<<blocks, WPB * 32>>>(y_pred, y_attack, out, nrows);
}

// round 5
// speedup vs baseline: 36.3339x; 36.3339x over previous
#include <cuda_runtime.h>
#include <math.h>

#define WPB 8           // warps per block
#define NC  1000        // classes
#define NK  10          // attack classes per row

__device__ __forceinline__ float pow9f(float x) {
    float x2 = x * x;
    float x4 = x2 * x2;
    float x8 = x4 * x4;
    return x8 * x;
}
__device__ __forceinline__ float pow10f(float x) {
    float x2 = x * x;
    float x4 = x2 * x2;
    float x8 = x4 * x4;
    return x8 * x2;
}
// y^(1/p) for y > 0 via MUFU lg2/ex2 (rel err ~1e-7 after /p)
__device__ __forceinline__ float rootf(float y, float inv_p) {
    return __powf(y, inv_p);
}

__global__ __launch_bounds__(WPB * 32)
void boilerplate_loss_kernel(const float* __restrict__ y_pred,
                             const int*   __restrict__ y_attack,
                             float*       __restrict__ out,
                             int nrows)
{
    __shared__ unsigned int smask[WPB][32];   // 1000-bit attack mask per warp/row

    const int warp = threadIdx.x >> 5;
    const int lane = threadIdx.x & 31;
    const int row  = blockIdx.x * WPB + warp;
    if (row >= nrows) return;

    // --- build attack bitmask + gather attack logits (lanes 0..9) ---
    smask[warp][lane] = 0u;
    __syncwarp();

    float xa = 0.0f;
    if (lane < NK) {
        int idx = y_attack[row * NK + lane];
        xa = __ldg(&y_pred[(size_t)row * NC + idx]);
        atomicOr(&smask[warp][idx >> 5], 1u << (idx & 31));
    }
    __syncwarp();

    // --- single pass: sum(exp(x)) and max over non-attack logits ---
    // 250 float4 per row, 32 lanes -> at most 8 iterations; fully unrolled
    // so all LDG.128s are batched (MLP ~8).
    const float4* rowp = reinterpret_cast<const float4*>(y_pred + (size_t)row * NC);
    float s  = 0.0f;
    float mx = -INFINITY;
    #pragma unroll 8
    for (int i = lane; i < NC / 4; i += 32) {
        float4 v = rowp[i];
        unsigned int bits = (smask[warp][i >> 3] >> ((i & 7) * 4)) & 0xFu;
        s += __expf(v.x); if (!(bits & 1u)) mx = fmaxf(mx, v.x);
        s += __expf(v.y); if (!(bits & 2u)) mx = fmaxf(mx, v.y);
        s += __expf(v.z); if (!(bits & 4u)) mx = fmaxf(mx, v.z);
        s += __expf(v.w); if (!(bits & 8u)) mx = fmaxf(mx, v.w);
    }
    #pragma unroll
    for (int o = 16; o > 0; o >>= 1) {
        s += __shfl_xor_sync(0xffffffffu, s, o);
        mx = fmaxf(mx, __shfl_xor_sync(0xffffffffu, mx, o));
    }

    // --- attack probs, min, macro loss ---
    float inv_s = __frcp_rn(s);
    float p = (lane < NK) ? (__expf(xa) * inv_s) : INFINITY;
    float pmin = p;
    #pragma unroll
    for (int o = 16; o > 0; o >>= 1)
        pmin = fminf(pmin, __shfl_xor_sync(0xffffffffu, pmin, o));
    float pmax_non = __expf(mx) * inv_s;
    float macro = pmax_non - pmin;

    // --- sorting term: diffs of consecutive attack probs, gen-mean p=9 (fp32) ---
    float pnext = __shfl_down_sync(0xffffffffu, p, 1);
    float term = 0.0f;
    if (lane < NK - 1) {
        float d  = pnext - p;                  // in [-1, 1]
        float sv = 5.0f + 5.0f * d;            // surject to [0, 10]
        term = pow9f(sv);
    }
    #pragma unroll
    for (int o = 16; o > 0; o >>= 1)
        term += __shfl_xor_sync(0xffffffffu, term, o);

    if (lane == 0) {
        float gm9 = rootf(term * (1.0f / 9.0f), 1.0f / 9.0f);
        float sorting = (gm9 - 5.0f) * 0.2f;
        float c0 = 5.0f + 5.0f * macro;
        float c1 = 5.0f + 5.0f * sorting;
        float m = (pow10f(c0) + pow10f(c1)) * 0.5f;
        float fin = rootf(m, 0.1f);
        out[row] = (fin - 5.0f) * 0.2f;
    }
}

extern "C" void kernel_launch(void* const* d_in, const int* in_sizes, int n_in,
                              void* d_out, int out_size)
{
    const float* y_pred   = (const float*)d_in[0];
    const int*   y_attack = (const int*)d_in[1];
    float*       out      = (float*)d_out;
    int nrows = in_sizes[1] / NK;   // 32768

    int blocks = (nrows + WPB - 1) / WPB;
    boilerplate_loss_kernel<<<blocks, WPB * 32>>>(y_pred, y_attack, out, nrows);
}

// round 7
// speedup vs baseline: 45.4267x; 1.2503x over previous
#include <cuda_runtime.h>
#include <math.h>

#define WPB 8           // warps per block
#define NC  1000        // classes
#define NF4 250         // float4 per row
#define NK  10          // attack classes per row

__device__ __forceinline__ float ex2f(float x) {
    float r; asm("ex2.approx.f32 %0, %1;" : "=f"(r) : "f"(x)); return r;
}
__device__ __forceinline__ float lg2f(float x) {
    float r; asm("lg2.approx.f32 %0, %1;" : "=f"(r) : "f"(x)); return r;
}
// packed (a,b) *= (c,c)  via mul.rn.f32x2 — halves FMUL count
__device__ __forceinline__ void mul2(float& a, float& b, unsigned long long cc) {
    unsigned long long in, ot;
    asm("mov.b64 %0, {%1, %2};" : "=l"(in) : "f"(a), "f"(b));
    asm("mul.rn.f32x2 %0, %1, %2;" : "=l"(ot) : "l"(in), "l"(cc));
    asm("mov.b64 {%0, %1}, %2;" : "=f"(a), "=f"(b) : "l"(ot));
}

__device__ __forceinline__ float pow9f(float x) {
    float x2 = x * x, x4 = x2 * x2, x8 = x4 * x4; return x8 * x;
}
__device__ __forceinline__ float pow10f(float x) {
    float x2 = x * x, x4 = x2 * x2, x8 = x4 * x4; return x8 * x2;
}
__device__ __forceinline__ float rootf(float y, float inv_p) {
    return ex2f(lg2f(y) * inv_p);
}

__global__ __launch_bounds__(WPB * 32)
void boilerplate_loss_kernel(const float* __restrict__ y_pred,
                             const int*   __restrict__ y_attack,
                             float*       __restrict__ out,
                             int nrows)
{
    __shared__ unsigned int smask[WPB][32];   // 1000-bit attack mask (rare path only)

    const int warp = threadIdx.x >> 5;
    const int lane = threadIdx.x & 31;
    const int row  = blockIdx.x * WPB + warp;
    if (row >= nrows) return;

    // --- build attack bitmask + gather attack logits (lanes 0..9) ---
    smask[warp][lane] = 0u;
    __syncwarp();

    float xa = 0.0f;
    if (lane < NK) {
        int idx = y_attack[row * NK + lane];
        xa = __ldg(&y_pred[(size_t)row * NC + idx]);
        atomicOr(&smask[warp][idx >> 5], 1u << (idx & 31));
    }
    __syncwarp();

    unsigned long long L2E2;
    asm("mov.b64 %0, {%1, %1};" : "=l"(L2E2) : "f"(1.4426950408889634f));

    // --- hot pass: sum(exp(x)) + UNCONDITIONAL max (no mask tests) ---
    const float4* rowp = reinterpret_cast<const float4*>(y_pred + (size_t)row * NC);
    float s0 = 0.f, s1 = 0.f, s2 = 0.f, s3 = 0.f;
    float mxa = -INFINITY;
    #pragma unroll
    for (int j = 0; j < 8; j++) {
        int i = lane + 32 * j;
        if (j < 7 || i < NF4) {
            float4 v = rowp[i];
            float ax = v.x, ay = v.y, az = v.z, aw = v.w;
            mul2(ax, ay, L2E2);
            mul2(az, aw, L2E2);
            s0 += ex2f(ax); s1 += ex2f(ay); s2 += ex2f(az); s3 += ex2f(aw);
            mxa = fmaxf(mxa, fmaxf(fmaxf(v.x, v.y), fmaxf(v.z, v.w)));
        }
    }
    float s = (s0 + s1) + (s2 + s3);
    #pragma unroll
    for (int o = 16; o > 0; o >>= 1) {
        s += __shfl_xor_sync(0xffffffffu, s, o);
        mxa = fmaxf(mxa, __shfl_xor_sync(0xffffffffu, mxa, o));
    }

    // --- max over attack logits; detect the rare argmax-is-attacked case ---
    float mxatt = (lane < NK) ? xa : -INFINITY;
    #pragma unroll
    for (int o = 16; o > 0; o >>= 1)
        mxatt = fmaxf(mxatt, __shfl_xor_sync(0xffffffffu, mxatt, o));

    float mx_non;
    if (mxa == mxatt) {
        // rare (~1% of rows), warp-uniform: masked rescan (row is L2-hot)
        float m = -INFINITY;
        #pragma unroll
        for (int j = 0; j < 8; j++) {
            int i = lane + 32 * j;
            if (j < 7 || i < NF4) {
                float4 v = rowp[i];
                unsigned int bits = (smask[warp][i >> 3] >> ((i & 7) * 4)) & 0xFu;
                if (!(bits & 1u)) m = fmaxf(m, v.x);
                if (!(bits & 2u)) m = fmaxf(m, v.y);
                if (!(bits & 4u)) m = fmaxf(m, v.z);
                if (!(bits & 8u)) m = fmaxf(m, v.w);
            }
        }
        #pragma unroll
        for (int o = 16; o > 0; o >>= 1)
            m = fmaxf(m, __shfl_xor_sync(0xffffffffu, m, o));
        mx_non = m;
    } else {
        mx_non = mxa;
    }

    // --- attack probs, min, macro loss ---
    float inv_s = __frcp_rn(s);
    float p = (lane < NK) ? (ex2f(xa * 1.4426950408889634f) * inv_s) : INFINITY;
    float pmin = p;
    #pragma unroll
    for (int o = 16; o > 0; o >>= 1)
        pmin = fminf(pmin, __shfl_xor_sync(0xffffffffu, pmin, o));
    float pmax_non = ex2f(mx_non * 1.4426950408889634f) * inv_s;
    float macro = pmax_non - pmin;

    // --- sorting term: diffs of consecutive attack probs, gen-mean p=9 ---
    float pnext = __shfl_down_sync(0xffffffffu, p, 1);
    float term = 0.0f;
    if (lane < NK - 1) {
        float d  = pnext - p;                  // in [-1, 1]
        float sv = 5.0f + 5.0f * d;            // surject to [0, 10]
        term = pow9f(sv);
    }
    #pragma unroll
    for (int o = 16; o > 0; o >>= 1)
        term += __shfl_xor_sync(0xffffffffu, term, o);

    if (lane == 0) {
        float gm9 = rootf(term * (1.0f / 9.0f), 1.0f / 9.0f);
        float sorting = (gm9 - 5.0f) * 0.2f;
        float c0 = 5.0f + 5.0f * macro;
        float c1 = 5.0f + 5.0f * sorting;
        float m = (pow10f(c0) + pow10f(c1)) * 0.5f;
        float fin = rootf(m, 0.1f);
        out[row] = (fin - 5.0f) * 0.2f;
    }
}

extern "C" void kernel_launch(void* const* d_in, const int* in_sizes, int n_in,
                              void* d_out, int out_size)
{
    const float* y_pred   = (const float*)d_in[0];
    const int*   y_attack = (const int*)d_in[1];
    float*       out      = (float*)d_out;
    int nrows = in_sizes[1] / NK;   // 32768

    int blocks = (nrows + WPB - 1) / WPB;
    boilerplate_loss_kernel<<<blocks, WPB * 32>>>(y_pred, y_attack, out, nrows);
}